// round 9
// baseline (speedup 1.0000x reference)
#include <cuda_runtime.h>
#include <cstdint>

#define NFIELDS 32
#define EMBED   64
#define NPAIRS  496
#define BATCH   2048
#define EMB_ROW (NFIELDS * EMBED)   // 2048 floats per batch
#define KER_ROW (NPAIRS * EMBED)    // 31744 floats per i row

#define BM      128                 // batches per block
#define PCHUNK  8                   // pairs per block (all share one r)
#define NCHUNKS 76                  // sum over r of ceil((31-r)/8)
#define NTHREADS 128

#define ASTR 68                     // raw A row stride (floats)
#define BSTR 68                     // raw B row stride
#define A_FLOATS (BM * ASTR)        // 8704
#define B_FLOATS (EMBED * BSTR)     // 4352

__device__ __forceinline__ uint32_t f2tf32(float x) {
    uint32_t r;
    asm("cvt.rna.tf32.f32 %0, %1;" : "=r"(r) : "f"(x));
    return r;
}

__device__ __forceinline__ void mma_tf32(float* d, uint32_t a0, uint32_t a1,
                                         uint32_t a2, uint32_t a3,
                                         uint32_t b0, uint32_t b1) {
    asm("mma.sync.aligned.m16n8k8.row.col.f32.tf32.tf32.f32 "
        "{%0,%1,%2,%3}, {%4,%5,%6,%7}, {%8,%9}, {%0,%1,%2,%3};"
        : "+f"(d[0]), "+f"(d[1]), "+f"(d[2]), "+f"(d[3])
        : "r"(a0), "r"(a1), "r"(a2), "r"(a3), "r"(b0), "r"(b1));
}

// N-dim permutation: GEMM col n holds physical i = phi(n),
//   phi(16k + 8h + 2m + u) = 16k + 4m + 2h + u.
// Staging stores physical row i at smem row rho(i) = phi^{-1}(i).
__device__ __forceinline__ int rho_row(int i) {
    return (i & 48) | (((i >> 1) & 1) << 3) | (((i >> 2) & 3) << 1) | (i & 1);
}

// Dense stage of K_p (64x64) -> raw smem [rho(i)*BSTR + j], tf32-rounded.
__device__ __forceinline__ void stage_B_raw(uint32_t* __restrict__ sB,
                                            const float* __restrict__ Kb, int t) {
    #pragma unroll
    for (int it = 0; it < 8; ++it) {
        int idx = it * NTHREADS + t;       // 0..1023 float4 slots
        int i   = idx >> 4;                // physical K row 0..63
        int j4  = idx & 15;
        float4 v = *(const float4*)(Kb + (size_t)i * KER_ROW + j4 * 4);
        uint4 w = { f2tf32(v.x), f2tf32(v.y), f2tf32(v.z), f2tf32(v.w) };
        *(uint4*)(sB + rho_row(i) * BSTR + j4 * 4) = w;
    }
}

__global__ void __launch_bounds__(NTHREADS, 2)
opn_mma_kernel(const float* __restrict__ emb, const float* __restrict__ ker,
               float* __restrict__ out)
{
    // smem (floats): sA raw 8704 | sB 4 x 4352 | sOut 1024  (108.5 KB)
    extern __shared__ __align__(16) uint32_t dynsmem[];
    uint32_t* sA   = dynsmem;
    uint32_t* sB   = dynsmem + A_FLOATS;
    float*    sOut = (float*)(sB + 4 * B_FLOATS);

    const int t    = threadIdx.x;
    const int w    = t >> 5;
    const int lane = t & 31;
    const int wp   = w & 1;     // pair within group
    const int ws   = w >> 1;    // batch strip: rows [ws*64, ws*64+64)
    const int m    = lane & 3;
    const int batch_base = blockIdx.x * BM;

    // ---- decode chunk id -> (r, first pair p0, #pairs np, first col c0) ----
    int cid = blockIdx.y, r = 0, pbase = 0;
    while (true) {
        int cnt = 31 - r;
        int nch = (cnt + PCHUNK - 1) >> 3;
        if (cid < nch) break;
        cid -= nch; pbase += cnt; ++r;
    }
    const int p0 = pbase + cid * PCHUNK;
    const int np = min(PCHUNK, (31 - r) - cid * PCHUNK);
    const int c0 = r + 1 + cid * PCHUNK;

    // ---- stage A raw: sA[b*ASTR + j] = tf32(emb[batch_base+b, r, j]) ----
    {
        const float* Pb = emb + (size_t)batch_base * EMB_ROW + (size_t)r * EMBED;
        #pragma unroll
        for (int it = 0; it < 16; ++it) {
            int idx = it * NTHREADS + t;   // 0..2047 float4 slots
            int b   = idx >> 4;            // 0..127
            int j4  = idx & 15;
            float4 v = *(const float4*)(Pb + (size_t)b * EMB_ROW + j4 * 4);
            uint4 w_ = { f2tf32(v.x), f2tf32(v.y), f2tf32(v.z), f2tf32(v.w) };
            *(uint4*)(sA + b * ASTR + j4 * 4) = w_;
        }
    }
    stage_B_raw(sB, ker + (size_t)p0 * EMBED, t);
    if (np > 1) stage_B_raw(sB + B_FLOATS, ker + (size_t)(p0 + 1) * EMBED, t);
    __syncthreads();

    const int aBase = (ws * 64 + (lane >> 2)) * ASTR + m;
    const int bBase = (lane >> 2) * BSTR + m;

    const int ng = (np + 1) >> 1;
    for (int g = 0; g < ng; ++g) {
        const int cur = (g & 1) * 2;
        const int nxt = cur ^ 2;

        if (g + 1 < ng) {
            int pi = 2 * (g + 1);
            stage_B_raw(sB + nxt * B_FLOATS, ker + (size_t)(p0 + pi) * EMBED, t);
            if (pi + 1 < np)
                stage_B_raw(sB + (nxt + 1) * B_FLOATS, ker + (size_t)(p0 + pi + 1) * EMBED, t);
        }

        const int j = 2 * g + wp;          // pair slot within chunk
        if (j < np) {
            const uint32_t* Bp = sB + (cur + wp) * B_FLOATS + bBase;
            const uint32_t* Ap = sA + aBase;

            float acc[4][8][4];
            #pragma unroll
            for (int mm = 0; mm < 4; ++mm)
                #pragma unroll
                for (int nt = 0; nt < 8; ++nt)
                    #pragma unroll
                    for (int u = 0; u < 4; ++u)
                        acc[mm][nt][u] = 0.f;

            #pragma unroll
            for (int kt = 0; kt < 8; ++kt) {
                uint32_t a[4][4];
                #pragma unroll
                for (int mm = 0; mm < 4; ++mm) {
                    const uint32_t* Am = Ap + mm * 16 * ASTR + kt * 8;
                    a[mm][0] = Am[0];
                    a[mm][1] = Am[8 * ASTR];
                    a[mm][2] = Am[4];
                    a[mm][3] = Am[8 * ASTR + 4];
                }
                uint32_t b0[8], b1[8];
                #pragma unroll
                for (int nt = 0; nt < 8; ++nt) {
                    const uint32_t* Bn = Bp + nt * 8 * BSTR + kt * 8;
                    b0[nt] = Bn[0];
                    b1[nt] = Bn[4];
                }
                #pragma unroll
                for (int mm = 0; mm < 4; ++mm)
                    #pragma unroll
                    for (int nt = 0; nt < 8; ++nt)
                        mma_tf32(acc[mm][nt], a[mm][0], a[mm][1], a[mm][2], a[mm][3],
                                 b0[nt], b1[nt]);
            }

            // ---- epilogue: dense float4 q loads via the N permutation ----
            const int c = c0 + j;
            #pragma unroll
            for (int mm = 0; mm < 4; ++mm) {
                const int row0 = ws * 64 + mm * 16 + (lane >> 2);
                const float* q0 = emb + (size_t)(batch_base + row0) * EMB_ROW + (size_t)c * EMBED;
                const float* q1 = q0 + 8 * EMB_ROW;

                float s0 = 0.f, s1 = 0.f;
                #pragma unroll
                for (int k = 0; k < 4; ++k) {
                    float4 qv0 = *(const float4*)(q0 + k * 16 + m * 4);
                    float4 qv1 = *(const float4*)(q1 + k * 16 + m * 4);
                    s0 += qv0.x * acc[mm][2 * k][0] + qv0.y * acc[mm][2 * k][1]
                        + qv0.z * acc[mm][2 * k + 1][0] + qv0.w * acc[mm][2 * k + 1][1];
                    s1 += qv1.x * acc[mm][2 * k][2] + qv1.y * acc[mm][2 * k][3]
                        + qv1.z * acc[mm][2 * k + 1][2] + qv1.w * acc[mm][2 * k + 1][3];
                }
                s0 += __shfl_xor_sync(0xffffffffu, s0, 1);
                s0 += __shfl_xor_sync(0xffffffffu, s0, 2);
                s1 += __shfl_xor_sync(0xffffffffu, s1, 1);
                s1 += __shfl_xor_sync(0xffffffffu, s1, 2);

                if (m == 0) {
                    sOut[row0 * PCHUNK + j]       = s0;
                    sOut[(row0 + 8) * PCHUNK + j] = s1;
                }
            }
        }
        __syncthreads();   // B double-buffer + sOut ordering
    }

    // ---- coalesced output sweep ----
    #pragma unroll
    for (int u = 0; u < 8; ++u) {
        int idx = t * 8 + u;               // 0..1023
        int b = idx >> 3;
        int jj = idx & 7;
        if (jj < np)
            out[(size_t)(batch_base + b) * NPAIRS + p0 + jj] = sOut[idx];
    }
}

#define SMEM_TOTAL ((A_FLOATS + 4 * B_FLOATS + BM * PCHUNK) * 4)   // 108.5 KB

extern "C" void kernel_launch(void* const* d_in, const int* in_sizes, int n_in,
                              void* d_out, int out_size) {
    const float* emb = (const float*)d_in[0];   // (2048, 32, 64) f32
    const float* ker = (const float*)d_in[1];   // (64, 496, 64) f32
    float* out = (float*)d_out;                 // (2048, 1, 496) f32
    (void)in_sizes; (void)n_in; (void)out_size;

    static bool attr_set = false;
    if (!attr_set) {
        cudaFuncSetAttribute(opn_mma_kernel,
                             cudaFuncAttributeMaxDynamicSharedMemorySize, SMEM_TOTAL);
        attr_set = true;
    }
    dim3 grid(BATCH / BM, NCHUNKS);
    opn_mma_kernel<<<grid, NTHREADS, SMEM_TOTAL>>>(emb, ker, out);
}